// round 16
// baseline (speedup 1.0000x reference)
#include <cuda_runtime.h>
#include <cuda_bf16.h>
#include <mma.h>
#include <math.h>

using namespace nvcuda;

// Problem-fixed maxima (shapes are fixed by the dataset)
#define NMAX      65536
#define NODESMAX  100000
#define EMAX      655360

// ---- scratch (device globals; no dynamic allocation allowed) ----
__device__ float g_qkvs[(size_t)NMAX * 512];   // per node: q[128] | k[128] | v[128] | skip[128]
__device__ float g_agg [(size_t)NMAX * 128];   // unnormalized attention numerator
__device__ float g_den [NMAX * 2];             // per-head softmax denominator
__device__ float g_lu  [NMAX];                 // last_update gathered to local rows
__device__ int   g_assoc[NODESMAX];            // global node id -> local row
__device__ float g_h   [(size_t)NMAX * 64];    // MLP output per node
__device__ int   g_mark[NMAX];                 // 1 if node row feeds the output
__device__ int   g_node_list[NMAX];            // compacted marked node rows
__device__ int   g_edge_list[EMAX];            // compacted edges with marked de
__device__ int   g_ncnt;                       // marked node count
__device__ int   g_ecnt;                       // kept edge count
__device__ float g_bias_tile[4][16][128];      // bias replicated over 16 rows (wmma acc init)

typedef unsigned long long ull;

// ---- packed f32x2 helpers (sm_103a FFMA2 path) ----
__device__ __forceinline__ ull pack2(float lo, float hi) {
    ull r;
    asm("mov.b64 %0, {%1, %2};" : "=l"(r)
        : "r"(__float_as_uint(lo)), "r"(__float_as_uint(hi)));
    return r;
}
__device__ __forceinline__ void unpack2(ull v, float &lo, float &hi) {
    unsigned int a, b;
    asm("mov.b64 {%0, %1}, %2;" : "=r"(a), "=r"(b) : "l"(v));
    lo = __uint_as_float(a);
    hi = __uint_as_float(b);
}
__device__ __forceinline__ ull fma2(ull a, ull b, ull c) {
    ull d;
    asm("fma.rn.f32x2 %0, %1, %2, %3;" : "=l"(d) : "l"(a), "l"(b), "l"(c));
    return d;
}
__device__ __forceinline__ void red4(float* p, float x, float y, float z, float w) {
    asm volatile("red.global.add.v4.f32 [%0], {%1, %2, %3, %4};"
                 :: "l"(p), "f"(x), "f"(y), "f"(z), "f"(w) : "memory");
}
__device__ __forceinline__ void red1(float* p, float x) {
    asm volatile("red.global.add.f32 [%0], %1;" :: "l"(p), "f"(x) : "memory");
}
__device__ __forceinline__ float to_tf32(float v) {
    unsigned int r;
    asm("cvt.rna.tf32.f32 %0, %1;" : "=r"(r) : "f"(v));
    return __uint_as_float(r);
}

// ============================================================================
// K0: zero accumulators, marks, lists, counts
// ============================================================================
__global__ void k_init(int Nn, int numNodes) {
    int i = blockIdx.x * 256 + threadIdx.x;
    int aggN = Nn * 128;
    if (i < aggN)      g_agg[i] = 0.f;
    if (i < Nn * 2)    g_den[i] = 0.f;
    if (i < numNodes)  g_assoc[i] = 0;
    if (i < Nn)      { g_mark[i] = 0; g_node_list[i] = 0; }
    if (i == 0)      { g_ncnt = 0; g_ecnt = 0; }
}

// ============================================================================
// K1: scatter assoc + gather last_update
// ============================================================================
__global__ void k_scatter(const int* __restrict__ n_id,
                          const float* __restrict__ last_update, int Nn) {
    int i = blockIdx.x * 256 + threadIdx.x;
    if (i < Nn) {
        int g = n_id[i];
        g_assoc[g] = i;
        g_lu[i] = last_update[g];
    }
}

// ============================================================================
// K1b: mark local rows referenced by the link-pred batch
// ============================================================================
__global__ void k_mark(const int* __restrict__ src, const int* __restrict__ dst,
                       const int* __restrict__ neg, int Bn) {
    int i = blockIdx.x * 256 + threadIdx.x;
    if      (i < Bn)     g_mark[g_assoc[src[i]]] = 1;
    else if (i < 2 * Bn) g_mark[g_assoc[dst[i - Bn]]] = 1;
    else if (i < 3 * Bn) g_mark[g_assoc[neg[i - 2 * Bn]]] = 1;
}

// ============================================================================
// K1c/K1d: compact marked nodes / edges whose destination is marked
// ============================================================================
__global__ void k_compact_nodes(int Nn) {
    int i = blockIdx.x * 256 + threadIdx.x;
    if (i < Nn && g_mark[i]) {
        int p = atomicAdd(&g_ncnt, 1);
        g_node_list[p] = i;
    }
}
__global__ void k_compact_edges(const int* __restrict__ edge_index, int E) {
    int e = blockIdx.x * 256 + threadIdx.x;
    if (e < E && g_mark[edge_index[E + e]]) {
        int p = atomicAdd(&g_ecnt, 1);
        g_edge_list[p] = e;
    }
}

// ============================================================================
// K1e: build bias tiles for wmma accumulator init (bias replicated 16 rows)
// ============================================================================
__global__ void k_bias(const float* __restrict__ bq, const float* __restrict__ bk,
                       const float* __restrict__ bv, const float* __restrict__ bs) {
    const float* b = (blockIdx.x == 0) ? bq : (blockIdx.x == 1) ? bk
                   : (blockIdx.x == 2) ? bv : bs;
    g_bias_tile[blockIdx.x][blockIdx.y][threadIdx.x] = b[threadIdx.x];
}

// ============================================================================
// K2: node GEMM via wmma tf32 m16n16k8 tensor path.
//     C[N,512] = z[N,256] @ [Wq|Wk|Wv|Wskip] + bias, all rows (tensor pipe is
//     cheap enough that q/skip compaction no longer pays for itself).
//     BM=128, BN=128 (one matrix per blockIdx.x), BK=16, 256 thr (8 warps),
//     warp w computes the m-strip [16w,16w+16) x 128 cols (8 acc fragments).
// ============================================================================
__global__ __launch_bounds__(256) void k_node_gemm(
    const int*   __restrict__ n_id,
    const float* __restrict__ memory, const float* __restrict__ pos_memory,
    const float* __restrict__ Wq, const float* __restrict__ Wk,
    const float* __restrict__ Wv, const float* __restrict__ Ws)
{
    __shared__ __align__(32) float Ah[128][20];   // A tile [m][k], tf32-rounded
    __shared__ __align__(32) float Bh[16][136];   // B tile [k][n], tf32-rounded

    const float* W;
    int bx = blockIdx.x;
    if      (bx == 0) W = Wq;
    else if (bx == 1) W = Wk;
    else if (bx == 2) W = Wv;
    else              W = Ws;

    int tid = threadIdx.x;
    int row0 = blockIdx.y << 7;
    int wid = tid >> 5;          // warp 0..7 -> m-strip 16*wid
    int m0  = wid << 4;

    int lr  = tid >> 2;          // A-load row (0..63), second row lr+64
    int lc4 = (tid & 3) << 2;    // A-load col within tile (0,4,8,12)
    int nid0 = n_id[row0 + lr];
    int nid1 = n_id[row0 + lr + 64];

    int bk_ = tid >> 5;          // B-load row in tile (0..7), second +8
    int bc  = (tid & 31) << 2;   // B-load col (float4)

    wmma::fragment<wmma::accumulator, 16, 16, 8, float> acc[8];
#pragma unroll
    for (int j = 0; j < 8; j++)
        wmma::load_matrix_sync(acc[j], &g_bias_tile[bx][0][j * 16], 128,
                               wmma::mem_row_major);

    for (int k0 = 0; k0 < 256; k0 += 16) {
        const float* srcm = (k0 < 128) ? memory : pos_memory;
        int kb = k0 & 127;
        float4 a0 = __ldg((const float4*)(srcm + (size_t)nid0 * 128 + kb + lc4));
        float4 a1 = __ldg((const float4*)(srcm + (size_t)nid1 * 128 + kb + lc4));
        float4 b0 = __ldg((const float4*)(W + (size_t)(k0 + bk_) * 128 + bc));
        float4 b1 = __ldg((const float4*)(W + (size_t)(k0 + bk_ + 8) * 128 + bc));
        __syncthreads();
        Ah[lr][lc4 + 0] = to_tf32(a0.x); Ah[lr][lc4 + 1] = to_tf32(a0.y);
        Ah[lr][lc4 + 2] = to_tf32(a0.z); Ah[lr][lc4 + 3] = to_tf32(a0.w);
        Ah[lr + 64][lc4 + 0] = to_tf32(a1.x); Ah[lr + 64][lc4 + 1] = to_tf32(a1.y);
        Ah[lr + 64][lc4 + 2] = to_tf32(a1.z); Ah[lr + 64][lc4 + 3] = to_tf32(a1.w);
        Bh[bk_][bc + 0] = to_tf32(b0.x); Bh[bk_][bc + 1] = to_tf32(b0.y);
        Bh[bk_][bc + 2] = to_tf32(b0.z); Bh[bk_][bc + 3] = to_tf32(b0.w);
        Bh[bk_ + 8][bc + 0] = to_tf32(b1.x); Bh[bk_ + 8][bc + 1] = to_tf32(b1.y);
        Bh[bk_ + 8][bc + 2] = to_tf32(b1.z); Bh[bk_ + 8][bc + 3] = to_tf32(b1.w);
        __syncthreads();
#pragma unroll
        for (int ks = 0; ks < 2; ks++) {
            wmma::fragment<wmma::matrix_a, 16, 16, 8, wmma::precision::tf32,
                           wmma::row_major> af;
            wmma::load_matrix_sync(af, &Ah[m0][ks * 8], 20);
#pragma unroll
            for (int j = 0; j < 8; j++) {
                wmma::fragment<wmma::matrix_b, 16, 16, 8, wmma::precision::tf32,
                               wmma::row_major> bf;
                wmma::load_matrix_sync(bf, &Bh[ks * 8][j * 16], 136);
                wmma::mma_sync(acc[j], af, bf, acc[j]);
            }
        }
    }

#pragma unroll
    for (int j = 0; j < 8; j++)
        wmma::store_matrix_sync(
            g_qkvs + (size_t)(row0 + m0) * 512 + (bx << 7) + j * 16,
            acc[j], 512, wmma::mem_row_major);
}

// ============================================================================
// K3: fused edge kernel over COMPACTED edges (marked destinations only).
//     BM=128 list entries/block, 256 threads, 8edge x 8col micro (R13 shape).
// ============================================================================
__global__ __launch_bounds__(256, 2) void k_edge(
    const int*   __restrict__ edge_index, const float* __restrict__ edge_t,
    const float* __restrict__ edge_msg,   const float* __restrict__ We,
    const float* __restrict__ be,         const float* __restrict__ time_w,
    const float* __restrict__ time_b,     int E)
{
    __shared__ int   s_se[128], s_de[128], s_eid[128];
    __shared__ float s_rel[128];
    __shared__ float s_tw[64], s_tb[64];
    __shared__ __align__(16) float As[16][128];
    __shared__ __align__(16) float Bs[16][128];

    int ecnt = g_ecnt;
    int e0 = blockIdx.x << 7;
    if (e0 >= ecnt) return;

    int tid = threadIdx.x;
    if (tid < 128) {
        int idx = e0 + tid;
        int eid = g_edge_list[idx < ecnt ? idx : ecnt - 1];
        s_eid[tid] = eid;
        int se = edge_index[eid];
        int de = edge_index[E + eid];
        s_se[tid] = se; s_de[tid] = de;
        s_rel[tid] = g_lu[se] - edge_t[eid];
    } else if (tid < 192) {
        s_tw[tid - 128] = time_w[tid - 128];
        s_tb[tid - 128] = time_b[tid - 128];
    }
    __syncthreads();

    int tx = tid & 15;   // cols tx*8 .. +7 ; head = tx>>3
    int ty = tid >> 4;   // edges ty*8 .. +7
    int lr = tid >> 1;   // A-load edge row 0..127
    int lc = (tid & 1) << 3;   // A-load col 0 or 8
    int bk_ = tid >> 5;
    int bc  = (tid & 31) << 2;

    ull acc[8][4];
#pragma unroll
    for (int i = 0; i < 8; i++)
#pragma unroll
        for (int j = 0; j < 4; j++) acc[i][j] = 0ULL;

    for (int k0 = 0; k0 < 128; k0 += 16) {
        float av[8];
        if (k0 < 64) {
            float rt = s_rel[lr];
#pragma unroll
            for (int ii = 0; ii < 8; ii++) {
                int c = k0 + lc + ii;
                av[ii] = cosf(rt * s_tw[c] + s_tb[c]);
            }
        } else {
            int er = s_eid[lr];
            float4 m0 = __ldg((const float4*)(edge_msg + (size_t)er * 64 + (k0 - 64) + lc));
            float4 m1 = __ldg((const float4*)(edge_msg + (size_t)er * 64 + (k0 - 64) + lc + 4));
            av[0] = m0.x; av[1] = m0.y; av[2] = m0.z; av[3] = m0.w;
            av[4] = m1.x; av[5] = m1.y; av[6] = m1.z; av[7] = m1.w;
        }
        float4 b0 = __ldg((const float4*)(We + (size_t)(k0 + bk_) * 128 + bc));
        float4 b1 = __ldg((const float4*)(We + (size_t)(k0 + bk_ + 8) * 128 + bc));
        __syncthreads();
#pragma unroll
        for (int ii = 0; ii < 8; ii++) As[lc + ii][lr] = av[ii];
        *(float4*)&Bs[bk_][bc]     = b0;
        *(float4*)&Bs[bk_ + 8][bc] = b1;
        __syncthreads();
#pragma unroll
        for (int kk = 0; kk < 16; kk++) {
            float a8[8];
            *(float4*)&a8[0] = *(const float4*)&As[kk][ty * 8];
            *(float4*)&a8[4] = *(const float4*)&As[kk][ty * 8 + 4];
            const ull* bp = (const ull*)&Bs[kk][tx * 8];
            ull bv0 = bp[0], bv1 = bp[1], bv2 = bp[2], bv3 = bp[3];
#pragma unroll
            for (int i = 0; i < 8; i++) {
                ull ad = pack2(a8[i], a8[i]);
                acc[i][0] = fma2(ad, bv0, acc[i][0]);
                acc[i][1] = fma2(ad, bv1, acc[i][1]);
                acc[i][2] = fma2(ad, bv2, acc[i][2]);
                acc[i][3] = fma2(ad, bv3, acc[i][3]);
            }
        }
    }

    float beb[8];
    *(float4*)&beb[0] = __ldg((const float4*)(be + tx * 8));
    *(float4*)&beb[4] = __ldg((const float4*)(be + tx * 8 + 4));

    // epilogue: 16 lanes (same ty) share an edge; lanes tx 0-7 = head0, 8-15 = head1
#pragma unroll
    for (int i = 0; i < 8; i++) {
        int el = ty * 8 + i;
        int de = s_de[el], se = s_se[el];
        float evv[8];
#pragma unroll
        for (int j = 0; j < 4; j++) {
            float lo, hi; unpack2(acc[i][j], lo, hi);
            evv[2 * j]     = lo + beb[2 * j];
            evv[2 * j + 1] = hi + beb[2 * j + 1];
        }
        const float* qp = g_qkvs + (size_t)de * 512 + tx * 8;
        const float* kp = g_qkvs + (size_t)se * 512 + 128 + tx * 8;
        float4 q0 = __ldg((const float4*)qp);
        float4 q1 = __ldg((const float4*)(qp + 4));
        float4 kk0 = __ldg((const float4*)kp);
        float4 kk1 = __ldg((const float4*)(kp + 4));
        float s = q0.x * (kk0.x + evv[0]) + q0.y * (kk0.y + evv[1])
                + q0.z * (kk0.z + evv[2]) + q0.w * (kk0.w + evv[3])
                + q1.x * (kk1.x + evv[4]) + q1.y * (kk1.y + evv[5])
                + q1.z * (kk1.z + evv[6]) + q1.w * (kk1.w + evv[7]);
        s += __shfl_xor_sync(0xffffffffu, s, 1);
        s += __shfl_xor_sync(0xffffffffu, s, 2);
        s += __shfl_xor_sync(0xffffffffu, s, 4);
        float ex = expf(s * 0.125f);   // / sqrt(HD=64)

        if (e0 + el < ecnt) {
            const float* vp = g_qkvs + (size_t)se * 512 + 256 + tx * 8;
            float4 v0 = __ldg((const float4*)vp);
            float4 v1 = __ldg((const float4*)(vp + 4));
            float* dst = g_agg + (size_t)de * 128 + tx * 8;
            red4(dst + 0, ex * (v0.x + evv[0]), ex * (v0.y + evv[1]),
                          ex * (v0.z + evv[2]), ex * (v0.w + evv[3]));
            red4(dst + 4, ex * (v1.x + evv[4]), ex * (v1.y + evv[5]),
                          ex * (v1.z + evv[6]), ex * (v1.w + evv[7]));
            if      (tx == 0) red1(&g_den[de * 2 + 0], ex);
            else if (tx == 8) red1(&g_den[de * 2 + 1], ex);
        }
    }
}

// ============================================================================
// K4: normalize + skip + MLP -> g_h, MARKED nodes only (64 list entries/block)
// ============================================================================
__global__ __launch_bounds__(256) void k_node_final(
    const float* __restrict__ mlp_w, const float* __restrict__ mlp_b)
{
    __shared__ float so[64][129];
    __shared__ __align__(16) float sw[16][64];
    __shared__ int s_nodes[64];
    int ncnt = g_ncnt;
    int base = blockIdx.x << 6;
    if (base >= ncnt) return;

    int t = threadIdx.x;
    if (t < 64) s_nodes[t] = g_node_list[base + t];
    __syncthreads();

    // stage normalized+skip node features [64 x 128]
#pragma unroll 1
    for (int r = 0; r < 32; r++) {
        int idx = r * 256 + t;
        int nl = idx >> 7, c = idx & 127;
        int node = s_nodes[nl];
        float d = g_den[node * 2 + (c >> 6)];
        so[nl][c] = g_agg[(size_t)node * 128 + c] / (d + 1e-16f)
                  + g_qkvs[(size_t)node * 512 + 384 + c];
    }

    int nl  = t >> 2;            // 0..63
    int col0 = (t & 3) << 4;     // 0,16,32,48
    ull accs[8];
#pragma unroll
    for (int j = 0; j < 8; j++) accs[j] = 0ULL;

#pragma unroll 1
    for (int d0 = 0; d0 < 128; d0 += 16) {
        __syncthreads();
        // load mlp_w chunk [16 x 64]
        {
            int wr = t >> 4, wc = (t & 15) << 2;
            *(float4*)&sw[wr][wc] = __ldg((const float4*)(mlp_w + (size_t)(d0 + wr) * 64 + wc));
        }
        __syncthreads();
#pragma unroll
        for (int d = 0; d < 16; d++) {
            float a0 = so[nl][d0 + d];
            ull ad = pack2(a0, a0);
            const ull* wp = (const ull*)&sw[d][col0];
#pragma unroll
            for (int j = 0; j < 8; j++) accs[j] = fma2(ad, wp[j], accs[j]);
        }
    }

    float outv[16];
#pragma unroll
    for (int j = 0; j < 8; j++) {
        float lo, hi; unpack2(accs[j], lo, hi);
        outv[2 * j]     = lo + __ldg(mlp_b + col0 + 2 * j);
        outv[2 * j + 1] = hi + __ldg(mlp_b + col0 + 2 * j + 1);
    }
    float* op = g_h + (size_t)s_nodes[nl] * 64 + col0;
#pragma unroll
    for (int j = 0; j < 4; j++)
        *(float4*)&op[4 * j] = *(float4*)&outv[4 * j];
}

// ============================================================================
// K5: link predictor.  blocks [0,B) -> pos (src,dst); [B,2B) -> neg (src,neg_dst)
// ============================================================================
__global__ __launch_bounds__(64) void k_link_pred(
    const int* __restrict__ src, const int* __restrict__ dst,
    const int* __restrict__ neg_dst,
    const float* __restrict__ lps_w, const float* __restrict__ lps_b,
    const float* __restrict__ lpd_w, const float* __restrict__ lpd_b,
    const float* __restrict__ lpf_w, const float* __restrict__ lpf_b,
    float* __restrict__ out, int Bn)
{
    __shared__ float sa[64], sb[64];
    __shared__ float red[2];
    int b = blockIdx.x;
    int t = threadIdx.x;
    int pos = (b < Bn);
    int bb = pos ? b : b - Bn;
    int sn = g_assoc[src[bb]];
    int dn = g_assoc[pos ? dst[bb] : neg_dst[bb]];
    sa[t] = g_h[(size_t)sn * 64 + t];
    sb[t] = g_h[(size_t)dn * 64 + t];
    __syncthreads();
    float hh = __ldg(lps_b + t) + __ldg(lpd_b + t);
#pragma unroll
    for (int d = 0; d < 64; d++)
        hh += sa[d] * __ldg(lps_w + d * 64 + t) + sb[d] * __ldg(lpd_w + d * 64 + t);
    hh = fmaxf(hh, 0.f);
    float p = hh * __ldg(lpf_w + t);
    p += __shfl_xor_sync(0xffffffffu, p, 16);
    p += __shfl_xor_sync(0xffffffffu, p, 8);
    p += __shfl_xor_sync(0xffffffffu, p, 4);
    p += __shfl_xor_sync(0xffffffffu, p, 2);
    p += __shfl_xor_sync(0xffffffffu, p, 1);
    if ((t & 31) == 0) red[t >> 5] = p;
    __syncthreads();
    if (t == 0) out[b] = red[0] + red[1] + __ldg(lpf_b);
}

// ============================================================================
extern "C" void kernel_launch(void* const* d_in, const int* in_sizes, int n_in,
                              void* d_out, int out_size)
{
    const float* memory      = (const float*)d_in[0];
    const float* pos_memory  = (const float*)d_in[1];
    const float* last_update = (const float*)d_in[2];
    const int*   n_id        = (const int*)  d_in[3];
    const int*   edge_index  = (const int*)  d_in[4];
    const float* edge_t      = (const float*)d_in[5];
    const float* edge_msg    = (const float*)d_in[6];
    const int*   src         = (const int*)  d_in[7];
    const int*   dst         = (const int*)  d_in[8];
    const int*   neg_dst     = (const int*)  d_in[9];
    const float* time_w      = (const float*)d_in[10];
    const float* time_b      = (const float*)d_in[11];
    const float* Wq          = (const float*)d_in[12];
    const float* bq          = (const float*)d_in[13];
    const float* Wk          = (const float*)d_in[14];
    const float* bk          = (const float*)d_in[15];
    const float* Wv          = (const float*)d_in[16];
    const float* bv          = (const float*)d_in[17];
    const float* We          = (const float*)d_in[18];
    const float* be          = (const float*)d_in[19];
    const float* Wskip       = (const float*)d_in[20];
    const float* bskip       = (const float*)d_in[21];
    const float* mlp_w       = (const float*)d_in[22];
    const float* mlp_b       = (const float*)d_in[23];
    const float* lps_w       = (const float*)d_in[24];
    const float* lps_b       = (const float*)d_in[25];
    const float* lpd_w       = (const float*)d_in[26];
    const float* lpd_b       = (const float*)d_in[27];
    const float* lpf_w       = (const float*)d_in[28];
    const float* lpf_b       = (const float*)d_in[29];

    int Nn       = in_sizes[3];   // 65536
    int numNodes = in_sizes[2];   // 100000
    int E        = in_sizes[5];   // 655360
    int Bn       = in_sizes[7];   // 4096
    float* out   = (float*)d_out;

    int initN = Nn * 128;
    k_init<<<(initN + 255) / 256, 256>>>(Nn, numNodes);
    k_scatter<<<(Nn + 255) / 256, 256>>>(n_id, last_update, Nn);
    k_mark<<<(3 * Bn + 255) / 256, 256>>>(src, dst, neg_dst, Bn);
    k_compact_nodes<<<(Nn + 255) / 256, 256>>>(Nn);
    k_compact_edges<<<(E + 255) / 256, 256>>>(edge_index, E);
    k_bias<<<dim3(4, 16), 128>>>(bq, bk, bv, bskip);

    dim3 gg(4, (unsigned)(Nn >> 7));
    k_node_gemm<<<gg, 256>>>(n_id, memory, pos_memory, Wq, Wk, Wv, Wskip);

    k_edge<<<(E + 127) / 128, 256>>>(edge_index, edge_t, edge_msg,
                                     We, be, time_w, time_b, E);

    k_node_final<<<(Nn + 63) / 64, 256>>>(mlp_w, mlp_b);

    k_link_pred<<<2 * Bn, 64>>>(src, dst, neg_dst,
                                lps_w, lps_b, lpd_w, lpd_b, lpf_w, lpf_b,
                                out, Bn);
}

// round 17
// speedup vs baseline: 1.3351x; 1.3351x over previous
#include <cuda_runtime.h>
#include <cuda_bf16.h>
#include <mma.h>
#include <math.h>

using namespace nvcuda;

// Problem-fixed maxima (shapes are fixed by the dataset)
#define NMAX      65536
#define NODESMAX  100000
#define EMAX      655360

// ---- scratch (device globals; no dynamic allocation allowed) ----
__device__ float g_kv  [(size_t)NMAX * 256];   // per node: k[128] | v[128]
__device__ float g_qc  [(size_t)NMAX * 128];   // q, DENSE by list position
__device__ float g_sc  [(size_t)NMAX * 128];   // skip, DENSE by list position
__device__ float g_agg [(size_t)NMAX * 128];   // unnormalized attention numerator
__device__ float g_den [NMAX * 2];             // per-head softmax denominator
__device__ float g_lu  [NMAX];                 // last_update gathered to local rows
__device__ int   g_assoc[NODESMAX];            // global node id -> local row
__device__ float g_h   [(size_t)NMAX * 64];    // MLP output per node
__device__ int   g_mark[NMAX];                 // 1 if node row feeds the output
__device__ int   g_node_list[NMAX];            // compacted marked node rows
__device__ int   g_listpos[NMAX];              // node row -> list position (marked)
__device__ int   g_edge_list[EMAX];            // compacted edges with marked de
__device__ int   g_ncnt;                       // marked node count
__device__ int   g_ecnt;                       // kept edge count
__device__ float g_bias_tile[4][16][128];      // bias replicated over 16 rows (wmma acc init)

typedef unsigned long long ull;

// ---- packed f32x2 helpers (sm_103a FFMA2 path) ----
__device__ __forceinline__ ull pack2(float lo, float hi) {
    ull r;
    asm("mov.b64 %0, {%1, %2};" : "=l"(r)
        : "r"(__float_as_uint(lo)), "r"(__float_as_uint(hi)));
    return r;
}
__device__ __forceinline__ void unpack2(ull v, float &lo, float &hi) {
    unsigned int a, b;
    asm("mov.b64 {%0, %1}, %2;" : "=r"(a), "=r"(b) : "l"(v));
    lo = __uint_as_float(a);
    hi = __uint_as_float(b);
}
__device__ __forceinline__ ull fma2(ull a, ull b, ull c) {
    ull d;
    asm("fma.rn.f32x2 %0, %1, %2, %3;" : "=l"(d) : "l"(a), "l"(b), "l"(c));
    return d;
}
__device__ __forceinline__ void red4(float* p, float x, float y, float z, float w) {
    asm volatile("red.global.add.v4.f32 [%0], {%1, %2, %3, %4};"
                 :: "l"(p), "f"(x), "f"(y), "f"(z), "f"(w) : "memory");
}
__device__ __forceinline__ void red1(float* p, float x) {
    asm volatile("red.global.add.f32 [%0], %1;" :: "l"(p), "f"(x) : "memory");
}
__device__ __forceinline__ float to_tf32(float v) {
    unsigned int r;
    asm("cvt.rna.tf32.f32 %0, %1;" : "=r"(r) : "f"(v));
    return __uint_as_float(r);
}

// ============================================================================
// K0: zero accumulators, marks, lists, counts
// ============================================================================
__global__ void k_init(int Nn, int numNodes) {
    int i = blockIdx.x * 256 + threadIdx.x;
    int aggN = Nn * 128;
    if (i < aggN)      g_agg[i] = 0.f;
    if (i < Nn * 2)    g_den[i] = 0.f;
    if (i < numNodes)  g_assoc[i] = 0;
    if (i < Nn)      { g_mark[i] = 0; g_node_list[i] = 0; g_listpos[i] = 0; }
    if (i == 0)      { g_ncnt = 0; g_ecnt = 0; }
}

// ============================================================================
// K1: scatter assoc + gather last_update
// ============================================================================
__global__ void k_scatter(const int* __restrict__ n_id,
                          const float* __restrict__ last_update, int Nn) {
    int i = blockIdx.x * 256 + threadIdx.x;
    if (i < Nn) {
        int g = n_id[i];
        g_assoc[g] = i;
        g_lu[i] = last_update[g];
    }
}

// ============================================================================
// K1b: mark local rows referenced by the link-pred batch
// ============================================================================
__global__ void k_mark(const int* __restrict__ src, const int* __restrict__ dst,
                       const int* __restrict__ neg, int Bn) {
    int i = blockIdx.x * 256 + threadIdx.x;
    if      (i < Bn)     g_mark[g_assoc[src[i]]] = 1;
    else if (i < 2 * Bn) g_mark[g_assoc[dst[i - Bn]]] = 1;
    else if (i < 3 * Bn) g_mark[g_assoc[neg[i - 2 * Bn]]] = 1;
}

// ============================================================================
// K1c/K1d: compact marked nodes / edges whose destination is marked
// ============================================================================
__global__ void k_compact_nodes(int Nn) {
    int i = blockIdx.x * 256 + threadIdx.x;
    if (i < Nn && g_mark[i]) {
        int p = atomicAdd(&g_ncnt, 1);
        g_node_list[p] = i;
        g_listpos[i] = p;
    }
}
__global__ void k_compact_edges(const int* __restrict__ edge_index, int E) {
    int e = blockIdx.x * 256 + threadIdx.x;
    if (e < E && g_mark[edge_index[E + e]]) {
        int p = atomicAdd(&g_ecnt, 1);
        g_edge_list[p] = e;
    }
}

// ============================================================================
// K1e: build bias tiles for wmma accumulator init (bias replicated 16 rows)
// ============================================================================
__global__ void k_bias(const float* __restrict__ bq, const float* __restrict__ bk,
                       const float* __restrict__ bv, const float* __restrict__ bs) {
    const float* b = (blockIdx.x == 0) ? bq : (blockIdx.x == 1) ? bk
                   : (blockIdx.x == 2) ? bv : bs;
    g_bias_tile[blockIdx.x][blockIdx.y][threadIdx.x] = b[threadIdx.x];
}

// ============================================================================
// K2: node GEMM via wmma tf32 m16n16k8, warp layout 4(m) x 2(n),
//     warp tile m32 x n64 (2 af x 4 bf -> 8 mmas; 0.19 B LDS per MAC).
//     bx 1 (k) / 2 (v): all rows -> g_kv (stride 256).
//     bx 0 (q) / 3 (skip): MARKED rows only via g_node_list, outputs DENSE
//     by list position -> g_qc / g_sc (stride 128), so wmma stores stay
//     contiguous.  Tail positions clamp to node_list[.]=0 -> writes land in
//     unused dense rows (benign, deterministic).
// ============================================================================
__global__ __launch_bounds__(256) void k_node_gemm(
    const int*   __restrict__ n_id,
    const float* __restrict__ memory, const float* __restrict__ pos_memory,
    const float* __restrict__ Wq, const float* __restrict__ Wk,
    const float* __restrict__ Wv, const float* __restrict__ Ws)
{
    __shared__ __align__(32) float Ah[128][20];   // A tile [m][k], tf32-rounded
    __shared__ __align__(32) float Bh[16][136];   // B tile [k][n], tf32-rounded
    __shared__ int s_rows[128];

    const float* W;
    int bx = blockIdx.x;
    if      (bx == 0) W = Wq;
    else if (bx == 1) W = Wk;
    else if (bx == 2) W = Wv;
    else              W = Ws;

    int row0 = blockIdx.y << 7;
    bool sel = (bx == 0) || (bx == 3);
    if (sel && row0 >= g_ncnt) return;

    int tid = threadIdx.x;
    if (tid < 128)
        s_rows[tid] = sel ? g_node_list[row0 + tid] : (row0 + tid);
    __syncthreads();

    int wid = tid >> 5;
    int wm = wid >> 1;           // 0..3  -> rows [32*wm, +32)
    int wn = wid & 1;            // 0..1  -> cols [64*wn, +64)

    int lr  = tid >> 2;          // A-load row (0..63), second row lr+64
    int lc4 = (tid & 3) << 2;    // A-load col within tile (0,4,8,12)
    int nid0 = n_id[s_rows[lr]];
    int nid1 = n_id[s_rows[lr + 64]];

    int bk_ = tid >> 5;          // B-load row in tile (0..7), second +8
    int bc  = (tid & 31) << 2;   // B-load col (float4)

    wmma::fragment<wmma::accumulator, 16, 16, 8, float> acc[2][4];
#pragma unroll
    for (int im = 0; im < 2; im++)
#pragma unroll
        for (int jn = 0; jn < 4; jn++)
            wmma::load_matrix_sync(acc[im][jn],
                                   &g_bias_tile[bx][0][wn * 64 + jn * 16], 128,
                                   wmma::mem_row_major);

    for (int k0 = 0; k0 < 256; k0 += 16) {
        const float* srcm = (k0 < 128) ? memory : pos_memory;
        int kb = k0 & 127;
        float4 a0 = __ldg((const float4*)(srcm + (size_t)nid0 * 128 + kb + lc4));
        float4 a1 = __ldg((const float4*)(srcm + (size_t)nid1 * 128 + kb + lc4));
        float4 b0 = __ldg((const float4*)(W + (size_t)(k0 + bk_) * 128 + bc));
        float4 b1 = __ldg((const float4*)(W + (size_t)(k0 + bk_ + 8) * 128 + bc));
        __syncthreads();
        Ah[lr][lc4 + 0] = to_tf32(a0.x); Ah[lr][lc4 + 1] = to_tf32(a0.y);
        Ah[lr][lc4 + 2] = to_tf32(a0.z); Ah[lr][lc4 + 3] = to_tf32(a0.w);
        Ah[lr + 64][lc4 + 0] = to_tf32(a1.x); Ah[lr + 64][lc4 + 1] = to_tf32(a1.y);
        Ah[lr + 64][lc4 + 2] = to_tf32(a1.z); Ah[lr + 64][lc4 + 3] = to_tf32(a1.w);
        Bh[bk_][bc + 0] = to_tf32(b0.x); Bh[bk_][bc + 1] = to_tf32(b0.y);
        Bh[bk_][bc + 2] = to_tf32(b0.z); Bh[bk_][bc + 3] = to_tf32(b0.w);
        Bh[bk_ + 8][bc + 0] = to_tf32(b1.x); Bh[bk_ + 8][bc + 1] = to_tf32(b1.y);
        Bh[bk_ + 8][bc + 2] = to_tf32(b1.z); Bh[bk_ + 8][bc + 3] = to_tf32(b1.w);
        __syncthreads();
#pragma unroll
        for (int ks = 0; ks < 2; ks++) {
            wmma::fragment<wmma::matrix_a, 16, 16, 8, wmma::precision::tf32,
                           wmma::row_major> af[2];
#pragma unroll
            for (int im = 0; im < 2; im++)
                wmma::load_matrix_sync(af[im], &Ah[wm * 32 + im * 16][ks * 8], 20);
#pragma unroll
            for (int jn = 0; jn < 4; jn++) {
                wmma::fragment<wmma::matrix_b, 16, 16, 8, wmma::precision::tf32,
                               wmma::row_major> bf;
                wmma::load_matrix_sync(bf, &Bh[ks * 8][wn * 64 + jn * 16], 136);
#pragma unroll
                for (int im = 0; im < 2; im++)
                    wmma::mma_sync(acc[im][jn], af[im], bf, acc[im][jn]);
            }
        }
    }

    // store: dense rows (row0 + m) in the chosen destination
#pragma unroll
    for (int im = 0; im < 2; im++) {
        int orow = row0 + wm * 32 + im * 16;
#pragma unroll
        for (int jn = 0; jn < 4; jn++) {
            int ocol = wn * 64 + jn * 16;
            float* dst;
            int ld;
            if      (bx == 0) { dst = g_qc + (size_t)orow * 128 + ocol;       ld = 128; }
            else if (bx == 1) { dst = g_kv + (size_t)orow * 256 + ocol;       ld = 256; }
            else if (bx == 2) { dst = g_kv + (size_t)orow * 256 + 128 + ocol; ld = 256; }
            else              { dst = g_sc + (size_t)orow * 128 + ocol;       ld = 128; }
            wmma::store_matrix_sync(dst, acc[im][jn], ld, wmma::mem_row_major);
        }
    }
}

// ============================================================================
// K3: fused edge kernel over COMPACTED edges (marked destinations only).
//     BM=128 list entries/block, 256 threads, 8edge x 8col micro (R13 shape).
//     q gathered from DENSE g_qc via listpos[de]; k/v from packed g_kv.
// ============================================================================
__global__ __launch_bounds__(256, 2) void k_edge(
    const int*   __restrict__ edge_index, const float* __restrict__ edge_t,
    const float* __restrict__ edge_msg,   const float* __restrict__ We,
    const float* __restrict__ be,         const float* __restrict__ time_w,
    const float* __restrict__ time_b,     int E)
{
    __shared__ int   s_se[128], s_de[128], s_eid[128], s_qrow[128];
    __shared__ float s_rel[128];
    __shared__ float s_tw[64], s_tb[64];
    __shared__ __align__(16) float As[16][128];
    __shared__ __align__(16) float Bs[16][128];

    int ecnt = g_ecnt;
    int e0 = blockIdx.x << 7;
    if (e0 >= ecnt) return;

    int tid = threadIdx.x;
    if (tid < 128) {
        int idx = e0 + tid;
        int eid = g_edge_list[idx < ecnt ? idx : ecnt - 1];
        s_eid[tid] = eid;
        int se = edge_index[eid];
        int de = edge_index[E + eid];
        s_se[tid] = se; s_de[tid] = de;
        s_qrow[tid] = g_listpos[de];
        s_rel[tid] = g_lu[se] - edge_t[eid];
    } else if (tid < 192) {
        s_tw[tid - 128] = time_w[tid - 128];
        s_tb[tid - 128] = time_b[tid - 128];
    }
    __syncthreads();

    int tx = tid & 15;   // cols tx*8 .. +7 ; head = tx>>3
    int ty = tid >> 4;   // edges ty*8 .. +7
    int lr = tid >> 1;   // A-load edge row 0..127
    int lc = (tid & 1) << 3;   // A-load col 0 or 8
    int bk_ = tid >> 5;
    int bc  = (tid & 31) << 2;

    ull acc[8][4];
#pragma unroll
    for (int i = 0; i < 8; i++)
#pragma unroll
        for (int j = 0; j < 4; j++) acc[i][j] = 0ULL;

    for (int k0 = 0; k0 < 128; k0 += 16) {
        float av[8];
        if (k0 < 64) {
            float rt = s_rel[lr];
#pragma unroll
            for (int ii = 0; ii < 8; ii++) {
                int c = k0 + lc + ii;
                av[ii] = cosf(rt * s_tw[c] + s_tb[c]);
            }
        } else {
            int er = s_eid[lr];
            float4 m0 = __ldg((const float4*)(edge_msg + (size_t)er * 64 + (k0 - 64) + lc));
            float4 m1 = __ldg((const float4*)(edge_msg + (size_t)er * 64 + (k0 - 64) + lc + 4));
            av[0] = m0.x; av[1] = m0.y; av[2] = m0.z; av[3] = m0.w;
            av[4] = m1.x; av[5] = m1.y; av[6] = m1.z; av[7] = m1.w;
        }
        float4 b0 = __ldg((const float4*)(We + (size_t)(k0 + bk_) * 128 + bc));
        float4 b1 = __ldg((const float4*)(We + (size_t)(k0 + bk_ + 8) * 128 + bc));
        __syncthreads();
#pragma unroll
        for (int ii = 0; ii < 8; ii++) As[lc + ii][lr] = av[ii];
        *(float4*)&Bs[bk_][bc]     = b0;
        *(float4*)&Bs[bk_ + 8][bc] = b1;
        __syncthreads();
#pragma unroll
        for (int kk = 0; kk < 16; kk++) {
            float a8[8];
            *(float4*)&a8[0] = *(const float4*)&As[kk][ty * 8];
            *(float4*)&a8[4] = *(const float4*)&As[kk][ty * 8 + 4];
            const ull* bp = (const ull*)&Bs[kk][tx * 8];
            ull bv0 = bp[0], bv1 = bp[1], bv2 = bp[2], bv3 = bp[3];
#pragma unroll
            for (int i = 0; i < 8; i++) {
                ull ad = pack2(a8[i], a8[i]);
                acc[i][0] = fma2(ad, bv0, acc[i][0]);
                acc[i][1] = fma2(ad, bv1, acc[i][1]);
                acc[i][2] = fma2(ad, bv2, acc[i][2]);
                acc[i][3] = fma2(ad, bv3, acc[i][3]);
            }
        }
    }

    float beb[8];
    *(float4*)&beb[0] = __ldg((const float4*)(be + tx * 8));
    *(float4*)&beb[4] = __ldg((const float4*)(be + tx * 8 + 4));

    // epilogue: 16 lanes (same ty) share an edge; lanes tx 0-7 = head0, 8-15 = head1
#pragma unroll
    for (int i = 0; i < 8; i++) {
        int el = ty * 8 + i;
        int de = s_de[el], se = s_se[el];
        float evv[8];
#pragma unroll
        for (int j = 0; j < 4; j++) {
            float lo, hi; unpack2(acc[i][j], lo, hi);
            evv[2 * j]     = lo + beb[2 * j];
            evv[2 * j + 1] = hi + beb[2 * j + 1];
        }
        const float* qp = g_qc + (size_t)s_qrow[el] * 128 + tx * 8;
        const float* kp = g_kv + (size_t)se * 256 + tx * 8;
        float4 q0 = __ldg((const float4*)qp);
        float4 q1 = __ldg((const float4*)(qp + 4));
        float4 kk0 = __ldg((const float4*)kp);
        float4 kk1 = __ldg((const float4*)(kp + 4));
        float s = q0.x * (kk0.x + evv[0]) + q0.y * (kk0.y + evv[1])
                + q0.z * (kk0.z + evv[2]) + q0.w * (kk0.w + evv[3])
                + q1.x * (kk1.x + evv[4]) + q1.y * (kk1.y + evv[5])
                + q1.z * (kk1.z + evv[6]) + q1.w * (kk1.w + evv[7]);
        s += __shfl_xor_sync(0xffffffffu, s, 1);
        s += __shfl_xor_sync(0xffffffffu, s, 2);
        s += __shfl_xor_sync(0xffffffffu, s, 4);
        float ex = expf(s * 0.125f);   // / sqrt(HD=64)

        if (e0 + el < ecnt) {
            const float* vp = g_kv + (size_t)se * 256 + 128 + tx * 8;
            float4 v0 = __ldg((const float4*)vp);
            float4 v1 = __ldg((const float4*)(vp + 4));
            float* dst = g_agg + (size_t)de * 128 + tx * 8;
            red4(dst + 0, ex * (v0.x + evv[0]), ex * (v0.y + evv[1]),
                          ex * (v0.z + evv[2]), ex * (v0.w + evv[3]));
            red4(dst + 4, ex * (v1.x + evv[4]), ex * (v1.y + evv[5]),
                          ex * (v1.z + evv[6]), ex * (v1.w + evv[7]));
            if      (tx == 0) red1(&g_den[de * 2 + 0], ex);
            else if (tx == 8) red1(&g_den[de * 2 + 1], ex);
        }
    }
}

// ============================================================================
// K4: normalize + skip + MLP -> g_h, MARKED nodes only (64 list entries/block)
//     skip read from DENSE g_sc (list position = base + nl).
// ============================================================================
__global__ __launch_bounds__(256) void k_node_final(
    const float* __restrict__ mlp_w, const float* __restrict__ mlp_b)
{
    __shared__ float so[64][129];
    __shared__ __align__(16) float sw[16][64];
    __shared__ int s_nodes[64];
    int ncnt = g_ncnt;
    int base = blockIdx.x << 6;
    if (base >= ncnt) return;

    int t = threadIdx.x;
    if (t < 64) s_nodes[t] = g_node_list[base + t];
    __syncthreads();

    // stage normalized+skip node features [64 x 128]
#pragma unroll 1
    for (int r = 0; r < 32; r++) {
        int idx = r * 256 + t;
        int nl = idx >> 7, c = idx & 127;
        int node = s_nodes[nl];
        float d = g_den[node * 2 + (c >> 6)];
        so[nl][c] = g_agg[(size_t)node * 128 + c] / (d + 1e-16f)
                  + g_sc[(size_t)(base + nl) * 128 + c];
    }

    int nl  = t >> 2;            // 0..63
    int col0 = (t & 3) << 4;     // 0,16,32,48
    ull accs[8];
#pragma unroll
    for (int j = 0; j < 8; j++) accs[j] = 0ULL;

#pragma unroll 1
    for (int d0 = 0; d0 < 128; d0 += 16) {
        __syncthreads();
        // load mlp_w chunk [16 x 64]
        {
            int wr = t >> 4, wc = (t & 15) << 2;
            *(float4*)&sw[wr][wc] = __ldg((const float4*)(mlp_w + (size_t)(d0 + wr) * 64 + wc));
        }
        __syncthreads();
#pragma unroll
        for (int d = 0; d < 16; d++) {
            float a0 = so[nl][d0 + d];
            ull ad = pack2(a0, a0);
            const ull* wp = (const ull*)&sw[d][col0];
#pragma unroll
            for (int j = 0; j < 8; j++) accs[j] = fma2(ad, wp[j], accs[j]);
        }
    }

    float outv[16];
#pragma unroll
    for (int j = 0; j < 8; j++) {
        float lo, hi; unpack2(accs[j], lo, hi);
        outv[2 * j]     = lo + __ldg(mlp_b + col0 + 2 * j);
        outv[2 * j + 1] = hi + __ldg(mlp_b + col0 + 2 * j + 1);
    }
    float* op = g_h + (size_t)s_nodes[nl] * 64 + col0;
#pragma unroll
    for (int j = 0; j < 4; j++)
        *(float4*)&op[4 * j] = *(float4*)&outv[4 * j];
}

// ============================================================================
// K5: link predictor.  blocks [0,B) -> pos (src,dst); [B,2B) -> neg (src,neg_dst)
// ============================================================================
__global__ __launch_bounds__(64) void k_link_pred(
    const int* __restrict__ src, const int* __restrict__ dst,
    const int* __restrict__ neg_dst,
    const float* __restrict__ lps_w, const float* __restrict__ lps_b,
    const float* __restrict__ lpd_w, const float* __restrict__ lpd_b,
    const float* __restrict__ lpf_w, const float* __restrict__ lpf_b,
    float* __restrict__ out, int Bn)
{
    __shared__ float sa[64], sb[64];
    __shared__ float red[2];
    int b = blockIdx.x;
    int t = threadIdx.x;
    int pos = (b < Bn);
    int bb = pos ? b : b - Bn;
    int sn = g_assoc[src[bb]];
    int dn = g_assoc[pos ? dst[bb] : neg_dst[bb]];
    sa[t] = g_h[(size_t)sn * 64 + t];
    sb[t] = g_h[(size_t)dn * 64 + t];
    __syncthreads();
    float hh = __ldg(lps_b + t) + __ldg(lpd_b + t);
#pragma unroll
    for (int d = 0; d < 64; d++)
        hh += sa[d] * __ldg(lps_w + d * 64 + t) + sb[d] * __ldg(lpd_w + d * 64 + t);
    hh = fmaxf(hh, 0.f);
    float p = hh * __ldg(lpf_w + t);
    p += __shfl_xor_sync(0xffffffffu, p, 16);
    p += __shfl_xor_sync(0xffffffffu, p, 8);
    p += __shfl_xor_sync(0xffffffffu, p, 4);
    p += __shfl_xor_sync(0xffffffffu, p, 2);
    p += __shfl_xor_sync(0xffffffffu, p, 1);
    if ((t & 31) == 0) red[t >> 5] = p;
    __syncthreads();
    if (t == 0) out[b] = red[0] + red[1] + __ldg(lpf_b);
}

// ============================================================================
extern "C" void kernel_launch(void* const* d_in, const int* in_sizes, int n_in,
                              void* d_out, int out_size)
{
    const float* memory      = (const float*)d_in[0];
    const float* pos_memory  = (const float*)d_in[1];
    const float* last_update = (const float*)d_in[2];
    const int*   n_id        = (const int*)  d_in[3];
    const int*   edge_index  = (const int*)  d_in[4];
    const float* edge_t      = (const float*)d_in[5];
    const float* edge_msg    = (const float*)d_in[6];
    const int*   src         = (const int*)  d_in[7];
    const int*   dst         = (const int*)  d_in[8];
    const int*   neg_dst     = (const int*)  d_in[9];
    const float* time_w      = (const float*)d_in[10];
    const float* time_b      = (const float*)d_in[11];
    const float* Wq          = (const float*)d_in[12];
    const float* bq          = (const float*)d_in[13];
    const float* Wk          = (const float*)d_in[14];
    const float* bk          = (const float*)d_in[15];
    const float* Wv          = (const float*)d_in[16];
    const float* bv          = (const float*)d_in[17];
    const float* We          = (const float*)d_in[18];
    const float* be          = (const float*)d_in[19];
    const float* Wskip       = (const float*)d_in[20];
    const float* bskip       = (const float*)d_in[21];
    const float* mlp_w       = (const float*)d_in[22];
    const float* mlp_b       = (const float*)d_in[23];
    const float* lps_w       = (const float*)d_in[24];
    const float* lps_b       = (const float*)d_in[25];
    const float* lpd_w       = (const float*)d_in[26];
    const float* lpd_b       = (const float*)d_in[27];
    const float* lpf_w       = (const float*)d_in[28];
    const float* lpf_b       = (const float*)d_in[29];

    int Nn       = in_sizes[3];   // 65536
    int numNodes = in_sizes[2];   // 100000
    int E        = in_sizes[5];   // 655360
    int Bn       = in_sizes[7];   // 4096
    float* out   = (float*)d_out;

    int initN = Nn * 128;
    k_init<<<(initN + 255) / 256, 256>>>(Nn, numNodes);
    k_scatter<<<(Nn + 255) / 256, 256>>>(n_id, last_update, Nn);
    k_mark<<<(3 * Bn + 255) / 256, 256>>>(src, dst, neg_dst, Bn);
    k_compact_nodes<<<(Nn + 255) / 256, 256>>>(Nn);
    k_compact_edges<<<(E + 255) / 256, 256>>>(edge_index, E);
    k_bias<<<dim3(4, 16), 128>>>(bq, bk, bv, bskip);

    dim3 gg(4, (unsigned)(Nn >> 7));
    k_node_gemm<<<gg, 256>>>(n_id, memory, pos_memory, Wq, Wk, Wv, Wskip);

    k_edge<<<(E + 127) / 128, 256>>>(edge_index, edge_t, edge_msg,
                                     We, be, time_w, time_b, E);

    k_node_final<<<(Nn + 63) / 64, 256>>>(mlp_w, mlp_b);

    k_link_pred<<<2 * Bn, 64>>>(src, dst, neg_dst,
                                lps_w, lps_b, lpd_w, lpd_b, lpf_w, lpf_b,
                                out, Bn);
}